// round 16
// baseline (speedup 1.0000x reference)
#include <cuda_runtime.h>
#include <cuda_fp16.h>
#include <cstdint>

#define BB 16
#define NN 576
#define DD 1024
#define HH 16
#define HD 64

// ---------------- scratch (static device globals; no allocation) ----------------
__device__ __align__(16) __half g_xh[(long)BB * NN * DD];        // x fp16
__device__ __align__(16) __half g_qkv[(long)BB * NN * 3 * DD];   // qkv fp16 packed
__device__ __align__(16) __half g_oh[(long)BB * NN * DD];        // o fp16
__device__ __align__(16) __half g_posh[(long)HH * NN * NN];      // pos fp16
__device__ __align__(16) __half g_wtqkv[(long)3 * DD * DD];      // [W_qk;W_v]^T fp16 [n][k]
__device__ __align__(16) __half g_wtp[(long)DD * DD];

// ---------------- helpers ------------------------------------------------------
__device__ __forceinline__ void mma_fp16(float& d0, float& d1, float& d2, float& d3,
                                         unsigned a0, unsigned a1, unsigned a2, unsigned a3,
                                         unsigned b0, unsigned b1) {
    asm volatile(
        "mma.sync.aligned.m16n8k16.row.col.f32.f16.f16.f32 "
        "{%0,%1,%2,%3}, {%4,%5,%6,%7}, {%8,%9}, {%0,%1,%2,%3};\n"
        : "+f"(d0), "+f"(d1), "+f"(d2), "+f"(d3)
        : "r"(a0), "r"(a1), "r"(a2), "r"(a3), "r"(b0), "r"(b1));
}

__device__ __forceinline__ void ldsm_x4(unsigned& r0, unsigned& r1, unsigned& r2,
                                        unsigned& r3, unsigned addr) {
    asm volatile("ldmatrix.sync.aligned.m8n8.x4.shared.b16 {%0,%1,%2,%3}, [%4];"
                 : "=r"(r0), "=r"(r1), "=r"(r2), "=r"(r3) : "r"(addr));
}

__device__ __forceinline__ unsigned packh2(__half x, __half y) {
    __half2 t;
    t.x = x; t.y = y;
    return *reinterpret_cast<unsigned*>(&t);
}

__device__ __forceinline__ unsigned pack2f(float x, float y) {
    return packh2(__float2half_rn(x), __float2half_rn(y));
}

// ---------------- prep: fp32 -> fp16 convert -----------------------------------
__global__ void cvt_half_k(const float* __restrict__ in, __half* __restrict__ out, int n) {
    int i = (blockIdx.x * 256 + threadIdx.x) * 4;
    if (i >= n) return;
    float4 a = *(const float4*)(in + i);
    __half2* o2 = (__half2*)(out + i);
    o2[0] = __floats2half2_rn(a.x, a.y);
    o2[1] = __floats2half2_rn(a.z, a.w);
}

// ---------------- prep: W [K][N] fp32 -> W^T [N][K] fp16 -----------------------
__global__ void transpose_w(const float* __restrict__ W, __half* __restrict__ Wt,
                            int K, int N) {
    __shared__ float t[32][33];
    const int k0 = blockIdx.y * 32, n0 = blockIdx.x * 32;
    const int tx = threadIdx.x, ty = threadIdx.y;
#pragma unroll
    for (int i = 0; i < 32; i += 8)
        t[ty + i][tx] = W[(long)(k0 + ty + i) * N + n0 + tx];
    __syncthreads();
#pragma unroll
    for (int i = 0; i < 32; i += 8)
        Wt[(long)(n0 + ty + i) * K + k0 + tx] = __float2half_rn(t[tx][ty + i]);
}

// ---------------- fp16 GEMM: C = A[M,K] @ Bt[N,K]^T ----------------------------
// 128x128 tile, K-chunk 32. 8 warps = 2m x 4n. ldmatrix fragment loads.
// LDG->reg->STS double-buffered staging (proven R13 path).
// CMODE: 0=fp32(+bias), 1=fp16.
#define GKP 20
#define G_WORDS (128 * GKP)
#define G_STG (2 * G_WORDS)
#define GS_SMEM (2 * G_STG * 4)               // 40960 B

template <int CMODE, bool BIAS>
__global__ __launch_bounds__(256, 2) void gemm_h(const __half* __restrict__ A,
                                                 const __half* __restrict__ Bt,
                                                 const float* __restrict__ bias,
                                                 void* __restrict__ C0,
                                                 int M, int K, int N) {
    extern __shared__ unsigned gsm[];
    const unsigned smA = (unsigned)__cvta_generic_to_shared(gsm);
    const int tid = threadIdx.x;
    const int warp = tid >> 5, lane = tid & 31;
    const int wm = (warp & 1) * 64, wn = (warp >> 1) * 32;
    const int gp = lane >> 2, tg = lane & 3;
    const int bm = blockIdx.y * 128, bn = blockIdx.x * 128;

    float acc[4][4][4];
#pragma unroll
    for (int i = 0; i < 4; i++)
#pragma unroll
        for (int j = 0; j < 4; j++)
#pragma unroll
            for (int r = 0; r < 4; r++) acc[i][j][r] = 0.0f;

    uint4 aS[2], bS[2];
    const __half* Ab = A + (long)bm * K;
    const __half* Bb = Bt + (long)bn * K;

    const int lm15 = lane & 15, lh = (lane >> 4) & 1, lq = (lane >> 3) & 1, l7 = lane & 7;

#define G_LOAD(k0)                                                              \
    {                                                                           \
        _Pragma("unroll") for (int i = 0; i < 2; i++) {                         \
            int idx = tid + 256 * i;                                            \
            int row = idx >> 2, seg = idx & 3;                                  \
            aS[i] = *(const uint4*)(Ab + (long)row * K + (k0) + seg * 8);       \
            bS[i] = *(const uint4*)(Bb + (long)row * K + (k0) + seg * 8);       \
        }                                                                       \
    }

#define G_STORE(s)                                                              \
    {                                                                           \
        unsigned* Ad = gsm + (s) * G_STG;                                       \
        unsigned* Bd = Ad + G_WORDS;                                            \
        _Pragma("unroll") for (int i = 0; i < 2; i++) {                         \
            int idx = tid + 256 * i;                                            \
            int row = idx >> 2, seg = idx & 3;                                  \
            *(uint4*)(Ad + row * GKP + seg * 4) = aS[i];                        \
            *(uint4*)(Bd + row * GKP + seg * 4) = bS[i];                        \
        }                                                                       \
    }

#define G_COMPUTE(s)                                                            \
    {                                                                           \
        const unsigned aBase = smA + (s) * G_STG * 4;                           \
        const unsigned bBase = aBase + G_WORDS * 4;                             \
        _Pragma("unroll") for (int st = 0; st < 2; st++) {                      \
            unsigned af[4][4];                                                  \
            _Pragma("unroll") for (int ma = 0; ma < 4; ma++)                    \
                ldsm_x4(af[ma][0], af[ma][1], af[ma][2], af[ma][3],             \
                        aBase + (((wm + ma * 16 + lm15) * GKP + st * 8 +        \
                                  lh * 4) << 2));                               \
            unsigned bf[4][2];                                                  \
            _Pragma("unroll") for (int p2 = 0; p2 < 2; p2++)                    \
                ldsm_x4(bf[2 * p2][0], bf[2 * p2][1], bf[2 * p2 + 1][0],        \
                        bf[2 * p2 + 1][1],                                      \
                        bBase + (((wn + p2 * 16 + lh * 8 + l7) * GKP +          \
                                  st * 8 + lq * 4) << 2));                      \
            _Pragma("unroll") for (int nb = 0; nb < 4; nb++)                    \
                _Pragma("unroll") for (int ma = 0; ma < 4; ma++)                \
                    mma_fp16(acc[ma][nb][0], acc[ma][nb][1], acc[ma][nb][2],    \
                             acc[ma][nb][3], af[ma][0], af[ma][1], af[ma][2],   \
                             af[ma][3], bf[nb][0], bf[nb][1]);                  \
        }                                                                       \
    }

    int s = 0;
    G_LOAD(0);
    G_STORE(0);
    __syncthreads();

    for (int k0 = 32; k0 < K; k0 += 32) {
        G_LOAD(k0);
        G_COMPUTE(s);
        G_STORE(s ^ 1);
        s ^= 1;
        __syncthreads();
    }
    G_COMPUTE(s);

#pragma unroll
    for (int ma = 0; ma < 4; ma++) {
        const long r0 = bm + wm + ma * 16 + gp;
        const long r1 = r0 + 8;
#pragma unroll
        for (int nb = 0; nb < 4; nb++) {
            const int col = bn + wn + nb * 8 + tg * 2;
            if (CMODE == 0) {
                float* C = (float*)C0;
                float2 v0 = make_float2(acc[ma][nb][0], acc[ma][nb][1]);
                float2 v1 = make_float2(acc[ma][nb][2], acc[ma][nb][3]);
                if (BIAS) {
                    const float bb0 = __ldg(bias + col), bb1 = __ldg(bias + col + 1);
                    v0.x += bb0; v0.y += bb1;
                    v1.x += bb0; v1.y += bb1;
                }
                *(float2*)(C + r0 * N + col) = v0;
                *(float2*)(C + r1 * N + col) = v1;
            } else {
                __half* C = (__half*)C0;
                *(unsigned*)(C + r0 * N + col) = pack2f(acc[ma][nb][0], acc[ma][nb][1]);
                *(unsigned*)(C + r1 * N + col) = pack2f(acc[ma][nb][2], acc[ma][nb][3]);
            }
        }
    }
#undef G_LOAD
#undef G_STORE
#undef G_COMPUTE
}

// ---------------- positional softmax -> fp16 (one block per row, loop heads) ---
__global__ __launch_bounds__(256) void pos_kernel(const float* __restrict__ rel,
                                                  const float* __restrict__ Wp,
                                                  const float* __restrict__ bp,
                                                  __half* __restrict__ pos) {
    const int n = blockIdx.x, tid = threadIdx.x;
    __shared__ float red[8];
    __shared__ float bcv;
    const float* r = rel + (long)n * NN * 3;

    const float r0x = r[tid * 3], r0y = r[tid * 3 + 1], r0z = r[tid * 3 + 2];
    const float r1x = r[(tid + 256) * 3], r1y = r[(tid + 256) * 3 + 1],
                r1z = r[(tid + 256) * 3 + 2];
    float r2x = 0, r2y = 0, r2z = 0;
    if (tid < 64) {
        r2x = r[(tid + 512) * 3]; r2y = r[(tid + 512) * 3 + 1];
        r2z = r[(tid + 512) * 3 + 2];
    }

    for (int h = 0; h < HH; h++) {
        const float w0 = Wp[h], w1 = Wp[HH + h], w2 = Wp[2 * HH + h], bb = bp[h];
        float s0 = r0x * w0 + r0y * w1 + r0z * w2 + bb;
        float s1 = r1x * w0 + r1y * w1 + r1z * w2 + bb;
        float s2 = (tid < 64) ? (r2x * w0 + r2y * w1 + r2z * w2 + bb) : -1e30f;

        float mx = fmaxf(fmaxf(s0, s1), s2);
#pragma unroll
        for (int o = 16; o; o >>= 1) mx = fmaxf(mx, __shfl_xor_sync(~0u, mx, o));
        if ((tid & 31) == 0) red[tid >> 5] = mx;
        __syncthreads();
        if (tid == 0) {
            float m = red[0];
            for (int i = 1; i < 8; i++) m = fmaxf(m, red[i]);
            bcv = m;
        }
        __syncthreads();
        mx = bcv;
        float e0 = expf(s0 - mx), e1 = expf(s1 - mx);
        float e2 = (tid < 64) ? expf(s2 - mx) : 0.0f;
        float sum = e0 + e1 + e2;
#pragma unroll
        for (int o = 16; o; o >>= 1) sum += __shfl_xor_sync(~0u, sum, o);
        if ((tid & 31) == 0) red[tid >> 5] = sum;
        __syncthreads();
        if (tid == 0) {
            float s = 0.f;
            for (int i = 0; i < 8; i++) s += red[i];
            bcv = 1.0f / s;
        }
        __syncthreads();
        const float inv = bcv;
        __half* out = pos + ((long)h * NN + n) * NN;
        out[tid] = __float2half_rn(e0 * inv);
        out[tid + 256] = __float2half_rn(e1 * inv);
        if (tid < 64) out[tid + 512] = __float2half_rn(e2 * inv);
        __syncthreads();
    }
}

// ---------------- fused one-pass attention (packed qkv, fp16 mma) ---------------
#define PB 36
#define QKVS 3072
#define FA_SMEM (4 * 64 * PB * 4)   // 36864 B

__global__ __launch_bounds__(256, 2) void fused_attn(
    const __half* __restrict__ qkv, const __half* __restrict__ pos,
    const float* __restrict__ gating, __half* __restrict__ o) {
    extern __shared__ unsigned smem[];
    const unsigned smA = (unsigned)__cvta_generic_to_shared(smem);
    unsigned* qs = smem;                   // [64][36] fp16x2 d-pairs
    unsigned* ks = qs + 64 * PB;           // [64 seq][36]
    unsigned* ps = ks + 64 * PB;           // [64 qrow][36] fp16x2 seq-pairs
    unsigned* vt = ps + 64 * PB;           // [64 d][36]  (V^T)
    const unsigned qA = smA;
    const unsigned kA = smA + 64 * PB * 4;
    const unsigned pA = smA + 2 * 64 * PB * 4;
    const unsigned vA = smA + 3 * 64 * PB * 4;

    const int tid = threadIdx.x, warp = tid >> 5, lane = tid & 31;
    const int gp = lane >> 2, tg = lane & 3;
    const int wm = (warp & 3) * 16;
    const int wh = warp >> 2;
    const int n0 = blockIdx.x * 64;
    const int b = blockIdx.y >> 4, h = blockIdx.y & 15;
    const int lm15 = lane & 15, lh2 = (lane >> 4) & 1, lq = (lane >> 3) & 1, l7 = lane & 7;

    const __half* qb = qkv + (long)b * NN * QKVS + (long)n0 * QKVS + h * 64;
    const __half* kb = qkv + (long)b * NN * QKVS + 1024 + h * 64;
    const __half* vb = qkv + (long)b * NN * QKVS + 2048 + h * 64;
    const __half* pbase = pos + ((long)h * NN + n0) * NN;

    // ---- load q tile ----
    {
        int idx = tid;
#pragma unroll
        for (int i = 0; i < 2; i++, idx += 256) {
            int r = idx >> 3, seg = idx & 7;
            *(uint4*)(qs + r * PB + seg * 4) = *(const uint4*)(qb + (long)r * QKVS + seg * 8);
        }
    }

    float Oc[8][4], Op[8][4];
#pragma unroll
    for (int i = 0; i < 8; i++)
#pragma unroll
        for (int j = 0; j < 4; j++) { Oc[i][j] = 0.0f; Op[i][j] = 0.0f; }
    float l0 = 0.0f, l1 = 0.0f;
    const float scale = 0.125f;

    const int vd = tid & 63, vkg = tid >> 6;

    for (int m0 = 0; m0 < NN; m0 += 64) {
        __syncthreads();
        {
            int idx = tid;
#pragma unroll
            for (int i = 0; i < 2; i++, idx += 256) {
                int r = idx >> 3, seg = idx & 7;
                *(uint4*)(ks + r * PB + seg * 4) =
                    *(const uint4*)(kb + (long)(m0 + r) * QKVS + seg * 8);
                *(uint4*)(ps + r * PB + seg * 4) =
                    *(const uint4*)(pbase + (long)r * NN + m0 + seg * 8);
            }
            const __half* vp = vb + (long)(m0 + vkg * 16) * QKVS + vd;
            __half vv[16];
#pragma unroll
            for (int j = 0; j < 16; j++) vv[j] = vp[(long)j * QKVS];
#pragma unroll
            for (int i = 0; i < 8; i++)
                vt[vd * PB + vkg * 8 + i] = packh2(vv[2 * i], vv[2 * i + 1]);
        }
        __syncthreads();

        // ---- S = q @ k^T over warp's 16x32 slice (plain fp16) ----
        float p[4][4];
#pragma unroll
        for (int i = 0; i < 4; i++)
#pragma unroll
            for (int j = 0; j < 4; j++) p[i][j] = 0.0f;

#pragma unroll
        for (int kc = 0; kc < 4; kc++) {
            const unsigned qoff = ((wm + lm15) * PB + kc * 8 + lh2 * 4) << 2;
            unsigned a0, a1, a2, a3;
            ldsm_x4(a0, a1, a2, a3, qA + qoff);
#pragma unroll
            for (int p2 = 0; p2 < 2; p2++) {
                const unsigned koff =
                    ((wh * 32 + p2 * 16 + lh2 * 8 + l7) * PB + kc * 8 + lq * 4) << 2;
                unsigned b0, b1, b2, b3;
                ldsm_x4(b0, b1, b2, b3, kA + koff);
                mma_fp16(p[2 * p2][0], p[2 * p2][1], p[2 * p2][2], p[2 * p2][3],
                         a0, a1, a2, a3, b0, b1);
                mma_fp16(p[2 * p2 + 1][0], p[2 * p2 + 1][1], p[2 * p2 + 1][2], p[2 * p2 + 1][3],
                         a0, a1, a2, a3, b2, b3);
            }
        }

        // ---- exp (no max-sub), row sums ----
#pragma unroll
        for (int na = 0; na < 4; na++) {
            p[na][0] = __expf(p[na][0] * scale);
            p[na][1] = __expf(p[na][1] * scale);
            p[na][2] = __expf(p[na][2] * scale);
            p[na][3] = __expf(p[na][3] * scale);
            l0 += p[na][0] + p[na][1];
            l1 += p[na][2] + p[na][3];
        }

        // ---- O_c += P@v, O_p += pos@v (plain fp16 k16) ----
#pragma unroll
        for (int s = 0; s < 2; s++) {
            unsigned Pa0 = pack2f(p[2 * s][0],     p[2 * s][1]);
            unsigned Pa1 = pack2f(p[2 * s][2],     p[2 * s][3]);
            unsigned Pa2 = pack2f(p[2 * s + 1][0], p[2 * s + 1][1]);
            unsigned Pa3 = pack2f(p[2 * s + 1][2], p[2 * s + 1][3]);

            unsigned pa0, pa1, pa2, pa3;
            const unsigned poff = ((wm + lm15) * PB + wh * 16 + s * 8 + lh2 * 4) << 2;
            ldsm_x4(pa0, pa1, pa2, pa3, pA + poff);
#pragma unroll
            for (int p2 = 0; p2 < 4; p2++) {
                const unsigned voff =
                    ((p2 * 16 + lh2 * 8 + l7) * PB + wh * 16 + s * 8 + lq * 4) << 2;
                unsigned b0a, b1a, b0b, b1b;
                ldsm_x4(b0a, b1a, b0b, b1b, vA + voff);
                mma_fp16(Oc[2 * p2][0], Oc[2 * p2][1], Oc[2 * p2][2], Oc[2 * p2][3],
                         Pa0, Pa1, Pa2, Pa3, b0a, b1a);
                mma_fp16(Op[2 * p2][0], Op[2 * p2][1], Op[2 * p2][2], Op[2 * p2][3],
                         pa0, pa1, pa2, pa3, b0a, b1a);
                mma_fp16(Oc[2 * p2 + 1][0], Oc[2 * p2 + 1][1], Oc[2 * p2 + 1][2], Oc[2 * p2 + 1][3],
                         Pa0, Pa1, Pa2, Pa3, b0b, b1b);
                mma_fp16(Op[2 * p2 + 1][0], Op[2 * p2 + 1][1], Op[2 * p2 + 1][2], Op[2 * p2 + 1][3],
                         pa0, pa1, pa2, pa3, b0b, b1b);
            }
        }
    }

    // ---- reduce row-sums within tg group ----
    l0 += __shfl_xor_sync(~0u, l0, 1); l0 += __shfl_xor_sync(~0u, l0, 2);
    l1 += __shfl_xor_sync(~0u, l1, 1); l1 += __shfl_xor_sync(~0u, l1, 2);

    // ---- combine warp-half partials via smem scratch ----
    float* sOc = (float*)smem;          // [64][65]
    float* sOp = sOc + 64 * 65;
    float* slb = sOp + 64 * 65;
    __syncthreads();
    if (wh == 1) {
#pragma unroll
        for (int nv = 0; nv < 8; nv++) {
            const int base = (wm + gp) * 65 + nv * 8 + 2 * tg;
            sOc[base]              = Oc[nv][0];
            sOc[base + 1]          = Oc[nv][1];
            sOc[base + 8 * 65]     = Oc[nv][2];
            sOc[base + 8 * 65 + 1] = Oc[nv][3];
            sOp[base]              = Op[nv][0];
            sOp[base + 1]          = Op[nv][1];
            sOp[base + 8 * 65]     = Op[nv][2];
            sOp[base + 8 * 65 + 1] = Op[nv][3];
        }
        slb[wm + gp] = l0;
        slb[wm + gp + 8] = l1;
    }
    __syncthreads();
    if (wh == 0) {
        const float g = 1.0f / (1.0f + __expf(-gating[h]));
        const float og = 1.0f - g;
        const float lt0 = l0 + slb[wm + gp];
        const float lt1 = l1 + slb[wm + gp + 8];
        const float c0 = og / lt0, c1 = og / lt1;
        const long row = n0 + wm + gp;
        __half* dst0 = o + ((long)b * NN + row) * DD + h * 64;
#pragma unroll
        for (int nv = 0; nv < 8; nv++) {
            const int base = (wm + gp) * 65 + nv * 8 + 2 * tg;
            float oc0 = Oc[nv][0] + sOc[base];
            float oc1 = Oc[nv][1] + sOc[base + 1];
            float oc2 = Oc[nv][2] + sOc[base + 8 * 65];
            float oc3 = Oc[nv][3] + sOc[base + 8 * 65 + 1];
            float op0 = Op[nv][0] + sOp[base];
            float op1 = Op[nv][1] + sOp[base + 1];
            float op2 = Op[nv][2] + sOp[base + 8 * 65];
            float op3 = Op[nv][3] + sOp[base + 8 * 65 + 1];
            __half* dst = dst0 + nv * 8 + 2 * tg;
            *(unsigned*)dst = pack2f(c0 * oc0 + g * op0, c0 * oc1 + g * op1);
            *(unsigned*)(dst + 8L * DD) = pack2f(c1 * oc2 + g * op2, c1 * oc3 + g * op3);
        }
    }
}

// ---------------- launch ----------------
extern "C" void kernel_launch(void* const* d_in, const int* in_sizes, int n_in,
                              void* d_out, int out_size) {
    const float* x      = (const float*)d_in[0];
    const float* W_qk   = (const float*)d_in[1];
    const float* W_v    = (const float*)d_in[2];
    const float* W_proj = (const float*)d_in[3];
    const float* b_proj = (const float*)d_in[4];
    const float* W_pos  = (const float*)d_in[5];
    const float* b_pos  = (const float*)d_in[6];
    const float* gating = (const float*)d_in[7];
    const float* rel    = (const float*)d_in[8];
    float* out = (float*)d_out;

    __half *xh, *qkv, *oh, *posh, *wtqkv, *wtp;
    cudaGetSymbolAddress((void**)&xh,    g_xh);
    cudaGetSymbolAddress((void**)&qkv,   g_qkv);
    cudaGetSymbolAddress((void**)&oh,    g_oh);
    cudaGetSymbolAddress((void**)&posh,  g_posh);
    cudaGetSymbolAddress((void**)&wtqkv, g_wtqkv);
    cudaGetSymbolAddress((void**)&wtp,   g_wtp);

    cudaFuncSetAttribute(gemm_h<0, true>,  cudaFuncAttributeMaxDynamicSharedMemorySize, GS_SMEM);
    cudaFuncSetAttribute(gemm_h<1, false>, cudaFuncAttributeMaxDynamicSharedMemorySize, GS_SMEM);
    cudaFuncSetAttribute(fused_attn, cudaFuncAttributeMaxDynamicSharedMemorySize, FA_SMEM);

    const int M = BB * NN;  // 9216

    // prep: x -> fp16; [W_qk | W_v] -> W^T fp16 (packed rows 0..3071); pos softmax
    cvt_half_k<<<(M * DD / 4 + 255) / 256, 256>>>(x, xh, M * DD);
    transpose_w<<<dim3(2 * DD / 32, DD / 32), dim3(32, 8)>>>(W_qk, wtqkv, DD, 2 * DD);
    transpose_w<<<dim3(DD / 32, DD / 32), dim3(32, 8)>>>(W_v, wtqkv + (long)2 * DD * DD, DD, DD);
    transpose_w<<<dim3(DD / 32, DD / 32), dim3(32, 8)>>>(W_proj, wtp, DD, DD);
    pos_kernel<<<NN, 256>>>(rel, W_pos, b_pos, posh);

    // qkv = x @ [W_qk | W_v]  (single fused projection, fp16)
    gemm_h<1, false><<<dim3(3 * DD / 128, M / 128), 256, GS_SMEM>>>(
        xh, wtqkv, nullptr, qkv, M, DD, 3 * DD);
    // fused one-pass attention -> o fp16
    fused_attn<<<dim3(NN / 64, BB * HH), 256, FA_SMEM>>>(qkv, posh, gating, oh);
    // out = o @ W_proj + b_proj  (fp32 + bias)
    gemm_h<0, true><<<dim3(DD / 128, M / 128), 256, GS_SMEM>>>(
        oh, wtp, b_proj, out, M, DD, DD);
}